// round 1
// baseline (speedup 1.0000x reference)
#include <cuda_runtime.h>
#include <cstddef>

#define NN 50000
#define NE 800000
#define DIN 128
#define DHID 128
#define DOUT 64

// Scratch (no cudaMalloc allowed)
__device__ float g_xw1[(size_t)NN * DHID];
__device__ float g_agg1[(size_t)NN * DHID];
__device__ float g_xw2[(size_t)NN * DOUT];
__device__ float g_deg[NN];
__device__ float g_dis[NN];

// ---------------- degree / norm ----------------
__global__ void k_zero_deg(int n) {
    int i = blockIdx.x * blockDim.x + threadIdx.x;
    if (i < n) g_deg[i] = 0.0f;
}

__global__ void k_count(const int* __restrict__ dst, int e) {
    int i = blockIdx.x * blockDim.x + threadIdx.x;
    if (i < e) atomicAdd(&g_deg[dst[i]], 1.0f);
}

__global__ void k_dis(int n) {
    int i = blockIdx.x * blockDim.x + threadIdx.x;
    if (i < n) g_dis[i] = rsqrtf(g_deg[i] + 1.0f);
}

// ---------------- SGEMM with fused GCN epilogue ----------------
// C = A @ W  (A: MxK row-major, W: KxN row-major)
// writes XW[r][c] = acc, AGG[r][c] = acc*dis[r]^2 + bias[c]
// RELU_IN applies relu to A elements on load (layer-2 input).
template <bool RELU_IN>
__global__ void sgemm_epi(const float* __restrict__ A,
                          const float* __restrict__ W,
                          const float* __restrict__ bias,
                          float* __restrict__ XW,
                          float* __restrict__ AGG,
                          int M, int K, int N)
{
    constexpr int BM = 64, BN = 64, BK = 16, TM = 4, TN = 4;
    __shared__ float As[BK][BM];   // transposed A tile
    __shared__ float Bs[BK][BN];

    const int tid = threadIdx.x;                 // 256 threads
    const int row0 = blockIdx.y * BM;
    const int col0 = blockIdx.x * BN;

    // A load: each thread one float4 along K
    const int a_r  = tid >> 2;                   // 0..63
    const int a_c4 = (tid & 3) * 4;              // 0,4,8,12
    // B load: each thread one float4 along N
    const int b_r  = tid >> 4;                   // 0..15
    const int b_c4 = (tid & 15) * 4;             // 0..60

    const int ty = tid >> 4;                     // 0..15 -> row group
    const int tx = tid & 15;                     // 0..15 -> col group

    float acc[TM][TN];
#pragma unroll
    for (int i = 0; i < TM; i++)
#pragma unroll
        for (int j = 0; j < TN; j++) acc[i][j] = 0.0f;

    for (int k0 = 0; k0 < K; k0 += BK) {
        // load A tile (guarded rows)
        float4 av = make_float4(0.f, 0.f, 0.f, 0.f);
        int gr = row0 + a_r;
        if (gr < M) av = *(const float4*)(A + (size_t)gr * K + k0 + a_c4);
        if (RELU_IN) {
            av.x = fmaxf(av.x, 0.f); av.y = fmaxf(av.y, 0.f);
            av.z = fmaxf(av.z, 0.f); av.w = fmaxf(av.w, 0.f);
        }
        As[a_c4 + 0][a_r] = av.x;
        As[a_c4 + 1][a_r] = av.y;
        As[a_c4 + 2][a_r] = av.z;
        As[a_c4 + 3][a_r] = av.w;

        // load B tile (always in-bounds: K,N multiples of BK,BN)
        *(float4*)&Bs[b_r][b_c4] =
            *(const float4*)(W + (size_t)(k0 + b_r) * N + col0 + b_c4);

        __syncthreads();

#pragma unroll
        for (int k = 0; k < BK; k++) {
            float4 rm = *(const float4*)&As[k][ty * TM];
            float4 rn = *(const float4*)&Bs[k][tx * TN];
            float m_[4] = {rm.x, rm.y, rm.z, rm.w};
            float n_[4] = {rn.x, rn.y, rn.z, rn.w};
#pragma unroll
            for (int i = 0; i < TM; i++)
#pragma unroll
                for (int j = 0; j < TN; j++)
                    acc[i][j] += m_[i] * n_[j];
        }
        __syncthreads();
    }

    // epilogue
#pragma unroll
    for (int i = 0; i < TM; i++) {
        int gr = row0 + ty * TM + i;
        if (gr >= M) continue;
        float d = g_dis[gr];
        float d2 = d * d;
#pragma unroll
        for (int j = 0; j < TN; j++) {
            int gc = col0 + tx * TN + j;
            float v = acc[i][j];
            XW[(size_t)gr * N + gc] = v;
            AGG[(size_t)gr * N + gc] = v * d2 + bias[gc];
        }
    }
}

// ---------------- edge scatter: D=128, one warp per edge ----------------
__global__ void k_scatter128(const int* __restrict__ src,
                             const int* __restrict__ dst,
                             const float* __restrict__ xw,
                             float* __restrict__ agg, int E)
{
    int e = (blockIdx.x * blockDim.x + threadIdx.x) >> 5;
    int lane = threadIdx.x & 31;
    if (e >= E) return;
    int s = src[e], d = dst[e];
    float nrm = g_dis[s] * g_dis[d];
    float4 v = *(const float4*)(xw + (size_t)s * 128 + lane * 4);
    float* p = agg + (size_t)d * 128 + lane * 4;
    asm volatile("red.global.add.v4.f32 [%0], {%1, %2, %3, %4};"
                 :: "l"(p), "f"(v.x * nrm), "f"(v.y * nrm),
                    "f"(v.z * nrm), "f"(v.w * nrm)
                 : "memory");
}

// ---------------- edge scatter: D=64, half warp per edge ----------------
__global__ void k_scatter64(const int* __restrict__ src,
                            const int* __restrict__ dst,
                            const float* __restrict__ xw,
                            float* __restrict__ agg, int E)
{
    int idx = blockIdx.x * blockDim.x + threadIdx.x;
    int e = idx >> 4;
    int q = idx & 15;
    if (e >= E) return;
    int s = src[e], d = dst[e];
    float nrm = g_dis[s] * g_dis[d];
    float4 v = *(const float4*)(xw + (size_t)s * 64 + q * 4);
    float* p = agg + (size_t)d * 64 + q * 4;
    asm volatile("red.global.add.v4.f32 [%0], {%1, %2, %3, %4};"
                 :: "l"(p), "f"(v.x * nrm), "f"(v.y * nrm),
                    "f"(v.z * nrm), "f"(v.w * nrm)
                 : "memory");
}

extern "C" void kernel_launch(void* const* d_in, const int* in_sizes, int n_in,
                              void* d_out, int out_size)
{
    const float* x  = (const float*)d_in[0];
    const int*   ei = (const int*)  d_in[1];
    const float* W1 = (const float*)d_in[2];
    const float* b1 = (const float*)d_in[3];
    const float* W2 = (const float*)d_in[4];
    const float* b2 = (const float*)d_in[5];
    float* out = (float*)d_out;

    const int N = in_sizes[0] / DIN;   // 50000
    const int E = in_sizes[1] / 2;     // 800000
    const int* src = ei;
    const int* dst = ei + E;

    float *xw1, *agg1, *xw2;
    cudaGetSymbolAddress((void**)&xw1,  g_xw1);
    cudaGetSymbolAddress((void**)&agg1, g_agg1);
    cudaGetSymbolAddress((void**)&xw2,  g_xw2);

    // degree + norm
    k_zero_deg<<<(N + 255) / 256, 256>>>(N);
    k_count  <<<(E + 255) / 256, 256>>>(dst, E);
    k_dis    <<<(N + 255) / 256, 256>>>(N);

    // layer 1: xw1 = x@W1 ; agg1 = xw1*dis^2 + b1
    {
        dim3 grid(DHID / 64, (N + 63) / 64);
        sgemm_epi<false><<<grid, 256>>>(x, W1, b1, xw1, agg1, N, DIN, DHID);
    }
    // layer 1 scatter: agg1[dst] += xw1[src] * dis[src]*dis[dst]
    {
        int warps = E;
        int blocks = (warps * 32 + 255) / 256;
        k_scatter128<<<blocks, 256>>>(src, dst, xw1, agg1, E);
    }
    // layer 2: xw2 = relu(agg1)@W2 ; out = xw2*dis^2 + b2
    {
        dim3 grid(DOUT / 64, (N + 63) / 64);
        sgemm_epi<true><<<grid, 256>>>(agg1, W2, b2, xw2, out, N, DHID, DOUT);
    }
    // layer 2 scatter into out
    {
        int halfwarps = E;
        int blocks = (halfwarps * 16 + 255) / 256;
        k_scatter64<<<blocks, 256>>>(src, dst, xw2, out, E);
    }
}

// round 2
// speedup vs baseline: 1.3284x; 1.3284x over previous
#include <cuda_runtime.h>
#include <cstddef>

#define NN 50000
#define NE 800000
#define DIN 128
#define DHID 128
#define DOUT 64

// ---------------- scratch (__device__ globals; no allocation) ----------------
__device__ float g_xw1[(size_t)NN * DHID];
__device__ float g_agg1[(size_t)NN * DHID];
__device__ float g_xw2[(size_t)NN * DOUT];
__device__ float g_dis[NN];
__device__ int   g_cnt[NN];
__device__ int   g_cur[NN];
__device__ int   g_off[NN + 1];
__device__ int   g_esrc[NE];

// ---------------- CSR build ----------------
__global__ void k_init(int n) {
    int i = blockIdx.x * blockDim.x + threadIdx.x;
    if (i < n) { g_cnt[i] = 0; g_cur[i] = 0; }
}

__global__ void k_hist(const int* __restrict__ dst, int e) {
    int i = blockIdx.x * blockDim.x + threadIdx.x;
    if (i < e) atomicAdd(&g_cnt[dst[i]], 1);
}

__global__ void k_dis(int n) {
    int i = blockIdx.x * blockDim.x + threadIdx.x;
    if (i < n) g_dis[i] = rsqrtf((float)g_cnt[i] + 1.0f);
}

// single-block exclusive scan over g_cnt -> g_off (warp-shuffle based)
__global__ void k_scan(int n) {
    __shared__ int warpsum[32];
    __shared__ int s_carry;
    const int tid = threadIdx.x, lane = tid & 31, wid = tid >> 5;
    if (tid == 0) s_carry = 0;
    __syncthreads();
    for (int base = 0; base < n; base += 1024) {
        int i = base + tid;
        int v = (i < n) ? g_cnt[i] : 0;
        int x = v;
#pragma unroll
        for (int o = 1; o < 32; o <<= 1) {
            int t = __shfl_up_sync(0xFFFFFFFFu, x, o);
            if (lane >= o) x += t;
        }
        if (lane == 31) warpsum[wid] = x;
        __syncthreads();
        if (wid == 0) {
            int w = warpsum[lane];
#pragma unroll
            for (int o = 1; o < 32; o <<= 1) {
                int t = __shfl_up_sync(0xFFFFFFFFu, w, o);
                if (lane >= o) w += t;
            }
            warpsum[lane] = w;
        }
        __syncthreads();
        int warpbase = (wid == 0) ? 0 : warpsum[wid - 1];
        int carry = s_carry;
        if (i < n) g_off[i] = carry + warpbase + x - v;
        __syncthreads();
        if (tid == 0) s_carry = carry + warpsum[31];
        __syncthreads();
    }
    if (threadIdx.x == 0) g_off[n] = s_carry;
}

__global__ void k_fill(const int* __restrict__ src, const int* __restrict__ dst, int e) {
    int i = blockIdx.x * blockDim.x + threadIdx.x;
    if (i < e) {
        int d = dst[i];
        int p = atomicAdd(&g_cur[d], 1);
        g_esrc[g_off[d] + p] = src[i];
    }
}

// ---------------- SGEMM: XW = op(A) @ W, op = optional relu ----------------
// BM=128, BK=16, TM=8 fixed; BN/TN template (128/8 for layer1, 64/4 for layer2)
template <int BN, int TN, bool RELU_IN>
__global__ void __launch_bounds__(256, 2)
gemm_xw(const float* __restrict__ A, const float* __restrict__ W,
        float* __restrict__ XW, int M, int K, int N)
{
    constexpr int BM = 128, BK = 16, TM = 8;
    __shared__ float As[BK][BM];   // transposed A tile
    __shared__ float Bs[BK][BN];

    const int tid  = threadIdx.x;          // 256 threads
    const int row0 = blockIdx.x * BM;
    const int tx   = tid & 15;              // col group
    const int ty   = tid >> 4;              // row group

    float acc[TM][TN];
#pragma unroll
    for (int i = 0; i < TM; i++)
#pragma unroll
        for (int j = 0; j < TN; j++) acc[i][j] = 0.0f;

    for (int k0 = 0; k0 < K; k0 += BK) {
        // A tile: 128x16 = 512 float4, 2 per thread
#pragma unroll
        for (int l = 0; l < 2; l++) {
            int idx = tid + l * 256;
            int r   = idx >> 2;
            int c4  = (idx & 3) * 4;
            float4 av = make_float4(0.f, 0.f, 0.f, 0.f);
            int gr = row0 + r;
            if (gr < M) av = *(const float4*)(A + (size_t)gr * K + k0 + c4);
            if (RELU_IN) {
                av.x = fmaxf(av.x, 0.f); av.y = fmaxf(av.y, 0.f);
                av.z = fmaxf(av.z, 0.f); av.w = fmaxf(av.w, 0.f);
            }
            As[c4 + 0][r] = av.x;
            As[c4 + 1][r] = av.y;
            As[c4 + 2][r] = av.z;
            As[c4 + 3][r] = av.w;
        }
        // B tile: 16 x BN
#pragma unroll
        for (int l = 0; l < (BK * BN / 4) / 256; l++) {
            int idx = tid + l * 256;
            int r   = idx / (BN / 4);
            int c4  = (idx % (BN / 4)) * 4;
            *(float4*)&Bs[r][c4] = *(const float4*)(W + (size_t)(k0 + r) * N + c4);
        }
        __syncthreads();

#pragma unroll
        for (int k = 0; k < BK; k++) {
            float a[TM], b[TN];
#pragma unroll
            for (int i = 0; i < TM; i += 4)
                *(float4*)&a[i] = *(const float4*)&As[k][ty * TM + i];
#pragma unroll
            for (int j = 0; j < TN; j += 4)
                *(float4*)&b[j] = *(const float4*)&Bs[k][tx * TN + j];
#pragma unroll
            for (int i = 0; i < TM; i++)
#pragma unroll
                for (int j = 0; j < TN; j++)
                    acc[i][j] += a[i] * b[j];
        }
        __syncthreads();
    }

#pragma unroll
    for (int i = 0; i < TM; i++) {
        int gr = row0 + ty * TM + i;
        if (gr >= M) continue;
#pragma unroll
        for (int j = 0; j < TN; j += 4) {
            float4 v = make_float4(acc[i][j], acc[i][j + 1], acc[i][j + 2], acc[i][j + 3]);
            *(float4*)(XW + (size_t)gr * N + tx * TN + j) = v;
        }
    }
}

// ---------------- CSR aggregation, D=128: one warp per node ----------------
// out[d] = dis[d] * ( sum_{s in nbr(d)} xw[s]*dis[s]  +  xw[d]*dis[d] ) + bias
__global__ void agg128(const float* __restrict__ xw,
                       const float* __restrict__ bias,
                       float* __restrict__ out, int n)
{
    int w = (blockIdx.x * blockDim.x + threadIdx.x) >> 5;
    int lane = threadIdx.x & 31;
    if (w >= n) return;
    int beg = g_off[w], end = g_off[w + 1];
    float dd = g_dis[w];

    float4 acc = *(const float4*)(xw + (size_t)w * 128 + lane * 4);
    acc.x *= dd; acc.y *= dd; acc.z *= dd; acc.w *= dd;

    int j = beg;
    for (; j + 4 <= end; j += 4) {
        int s0 = g_esrc[j], s1 = g_esrc[j + 1], s2 = g_esrc[j + 2], s3 = g_esrc[j + 3];
        float n0 = g_dis[s0], n1 = g_dis[s1], n2 = g_dis[s2], n3 = g_dis[s3];
        float4 v0 = *(const float4*)(xw + (size_t)s0 * 128 + lane * 4);
        float4 v1 = *(const float4*)(xw + (size_t)s1 * 128 + lane * 4);
        float4 v2 = *(const float4*)(xw + (size_t)s2 * 128 + lane * 4);
        float4 v3 = *(const float4*)(xw + (size_t)s3 * 128 + lane * 4);
        acc.x += v0.x * n0; acc.y += v0.y * n0; acc.z += v0.z * n0; acc.w += v0.w * n0;
        acc.x += v1.x * n1; acc.y += v1.y * n1; acc.z += v1.z * n1; acc.w += v1.w * n1;
        acc.x += v2.x * n2; acc.y += v2.y * n2; acc.z += v2.z * n2; acc.w += v2.w * n2;
        acc.x += v3.x * n3; acc.y += v3.y * n3; acc.z += v3.z * n3; acc.w += v3.w * n3;
    }
    for (; j < end; j++) {
        int s = g_esrc[j];
        float ns = g_dis[s];
        float4 v = *(const float4*)(xw + (size_t)s * 128 + lane * 4);
        acc.x += v.x * ns; acc.y += v.y * ns; acc.z += v.z * ns; acc.w += v.w * ns;
    }
    float4 b = *(const float4*)(bias + lane * 4);
    acc.x = acc.x * dd + b.x;
    acc.y = acc.y * dd + b.y;
    acc.z = acc.z * dd + b.z;
    acc.w = acc.w * dd + b.w;
    *(float4*)(out + (size_t)w * 128 + lane * 4) = acc;
}

// ---------------- CSR aggregation, D=64: one warp per node (float2/lane) ----
__global__ void agg64(const float* __restrict__ xw,
                      const float* __restrict__ bias,
                      float* __restrict__ out, int n)
{
    int w = (blockIdx.x * blockDim.x + threadIdx.x) >> 5;
    int lane = threadIdx.x & 31;
    if (w >= n) return;
    int beg = g_off[w], end = g_off[w + 1];
    float dd = g_dis[w];

    float2 acc = *(const float2*)(xw + (size_t)w * 64 + lane * 2);
    acc.x *= dd; acc.y *= dd;

    int j = beg;
    for (; j + 4 <= end; j += 4) {
        int s0 = g_esrc[j], s1 = g_esrc[j + 1], s2 = g_esrc[j + 2], s3 = g_esrc[j + 3];
        float n0 = g_dis[s0], n1 = g_dis[s1], n2 = g_dis[s2], n3 = g_dis[s3];
        float2 v0 = *(const float2*)(xw + (size_t)s0 * 64 + lane * 2);
        float2 v1 = *(const float2*)(xw + (size_t)s1 * 64 + lane * 2);
        float2 v2 = *(const float2*)(xw + (size_t)s2 * 64 + lane * 2);
        float2 v3 = *(const float2*)(xw + (size_t)s3 * 64 + lane * 2);
        acc.x += v0.x * n0; acc.y += v0.y * n0;
        acc.x += v1.x * n1; acc.y += v1.y * n1;
        acc.x += v2.x * n2; acc.y += v2.y * n2;
        acc.x += v3.x * n3; acc.y += v3.y * n3;
    }
    for (; j < end; j++) {
        int s = g_esrc[j];
        float ns = g_dis[s];
        float2 v = *(const float2*)(xw + (size_t)s * 64 + lane * 2);
        acc.x += v.x * ns; acc.y += v.y * ns;
    }
    float2 b = *(const float2*)(bias + lane * 2);
    acc.x = acc.x * dd + b.x;
    acc.y = acc.y * dd + b.y;
    *(float2*)(out + (size_t)w * 64 + lane * 2) = acc;
}

extern "C" void kernel_launch(void* const* d_in, const int* in_sizes, int n_in,
                              void* d_out, int out_size)
{
    const float* x  = (const float*)d_in[0];
    const int*   ei = (const int*)  d_in[1];
    const float* W1 = (const float*)d_in[2];
    const float* b1 = (const float*)d_in[3];
    const float* W2 = (const float*)d_in[4];
    const float* b2 = (const float*)d_in[5];
    float* out = (float*)d_out;

    const int N = in_sizes[0] / DIN;   // 50000
    const int E = in_sizes[1] / 2;     // 800000
    const int* src = ei;
    const int* dst = ei + E;

    float *xw1, *agg1, *xw2;
    cudaGetSymbolAddress((void**)&xw1,  g_xw1);
    cudaGetSymbolAddress((void**)&agg1, g_agg1);
    cudaGetSymbolAddress((void**)&xw2,  g_xw2);

    // CSR build + norms
    k_init<<<(N + 255) / 256, 256>>>(N);
    k_hist<<<(E + 255) / 256, 256>>>(dst, E);
    k_dis <<<(N + 255) / 256, 256>>>(N);
    k_scan<<<1, 1024>>>(N);
    k_fill<<<(E + 255) / 256, 256>>>(src, dst, E);

    const int gemm_grid = (N + 127) / 128;

    // layer 1: xw1 = x @ W1 ; agg1 = norm-agg(xw1) + b1
    gemm_xw<128, 8, false><<<gemm_grid, 256>>>(x, W1, xw1, N, DIN, DHID);
    agg128<<<(N * 32 + 255) / 256, 256>>>(xw1, b1, agg1, N);

    // layer 2: xw2 = relu(agg1) @ W2 ; out = norm-agg(xw2) + b2
    gemm_xw<64, 4, true><<<gemm_grid, 256>>>(agg1, W2, xw2, N, DHID, DOUT);
    agg64<<<(N * 32 + 255) / 256, 256>>>(xw2, b2, out, N);
}

// round 3
// speedup vs baseline: 1.4816x; 1.1153x over previous
#include <cuda_runtime.h>
#include <cstddef>

#define NN 50000
#define NE 800000
#define DIN 128
#define DHID 128
#define DOUT 64
#define NB   ((NN + 1023) / 1024)   // 49 scan blocks

// ---------------- scratch (__device__ globals; no allocation) ----------------
__device__ float g_xw1[(size_t)NN * DHID];   // pre-scaled by dis[row]
__device__ float g_agg1[(size_t)NN * DHID];
__device__ float g_xw2[(size_t)NN * DOUT];   // pre-scaled by dis[row]
__device__ float g_dis[NN];
__device__ int   g_cnt[NN];
__device__ int   g_cur[NN];
__device__ int   g_off[NN + 1];
__device__ int   g_esrc[NE];
__device__ int   g_bsum[NB];
__device__ int   g_bpre[NB];

// ---------------- CSR build ----------------
__global__ void k_init(int n) {
    int i = blockIdx.x * blockDim.x + threadIdx.x;
    if (i < n) { g_cnt[i] = 0; g_cur[i] = 0; }
}

__global__ void k_hist(const int* __restrict__ dst, int e) {
    int i = blockIdx.x * blockDim.x + threadIdx.x;
    if (i < e) atomicAdd(&g_cnt[dst[i]], 1);
}

// phase A: per-block exclusive scan of 1024 counts; block total to g_bsum
__global__ void k_scanA(int n) {
    __shared__ int warpsum[32];
    const int tid = threadIdx.x, lane = tid & 31, wid = tid >> 5;
    int i = blockIdx.x * 1024 + tid;
    int v = (i < n) ? g_cnt[i] : 0;
    int x = v;
#pragma unroll
    for (int o = 1; o < 32; o <<= 1) {
        int t = __shfl_up_sync(0xFFFFFFFFu, x, o);
        if (lane >= o) x += t;
    }
    if (lane == 31) warpsum[wid] = x;
    __syncthreads();
    if (wid == 0) {
        int w = warpsum[lane];
#pragma unroll
        for (int o = 1; o < 32; o <<= 1) {
            int t = __shfl_up_sync(0xFFFFFFFFu, w, o);
            if (lane >= o) w += t;
        }
        warpsum[lane] = w;
    }
    __syncthreads();
    int warpbase = (wid == 0) ? 0 : warpsum[wid - 1];
    if (i < n) g_off[i] = warpbase + x - v;      // local exclusive
    if (tid == 1023) g_bsum[blockIdx.x] = warpsum[31];
}

// phase B: serial exclusive scan of NB block sums (NB=49, trivial)
__global__ void k_scanB(int n, int nb) {
    int run = 0;
    for (int b = 0; b < nb; b++) { g_bpre[b] = run; run += g_bsum[b]; }
    g_off[n] = run;
}

// phase C: add block prefix; also compute dis = rsqrt(deg+1)
__global__ void k_scanC(int n) {
    int i = blockIdx.x * blockDim.x + threadIdx.x;
    if (i < n) {
        g_off[i] += g_bpre[i >> 10];
        g_dis[i] = rsqrtf((float)g_cnt[i] + 1.0f);
    }
}

__global__ void k_fill(const int* __restrict__ src, const int* __restrict__ dst, int e) {
    int i = blockIdx.x * blockDim.x + threadIdx.x;
    if (i < e) {
        int d = dst[i];
        int p = atomicAdd(&g_cur[d], 1);
        g_esrc[g_off[d] + p] = src[i];
    }
}

// ---------------- SGEMM: XWS = (op(A) @ W) * dis[row] ----------------
// BM=128, BK=16, TM=8 fixed; BN/TN template (128/8 layer1, 64/4 layer2)
template <int BN, int TN, bool RELU_IN>
__global__ void __launch_bounds__(256, 2)
gemm_xws(const float* __restrict__ A, const float* __restrict__ W,
         float* __restrict__ XWS, int M, int K, int N)
{
    constexpr int BM = 128, BK = 16, TM = 8;
    __shared__ float As[BK][BM];
    __shared__ float Bs[BK][BN];

    const int tid  = threadIdx.x;           // 256 threads
    const int row0 = blockIdx.x * BM;
    const int tx   = tid & 15;
    const int ty   = tid >> 4;

    float acc[TM][TN];
#pragma unroll
    for (int i = 0; i < TM; i++)
#pragma unroll
        for (int j = 0; j < TN; j++) acc[i][j] = 0.0f;

    for (int k0 = 0; k0 < K; k0 += BK) {
#pragma unroll
        for (int l = 0; l < 2; l++) {
            int idx = tid + l * 256;
            int r   = idx >> 2;
            int c4  = (idx & 3) * 4;
            float4 av = make_float4(0.f, 0.f, 0.f, 0.f);
            int gr = row0 + r;
            if (gr < M) av = *(const float4*)(A + (size_t)gr * K + k0 + c4);
            if (RELU_IN) {
                av.x = fmaxf(av.x, 0.f); av.y = fmaxf(av.y, 0.f);
                av.z = fmaxf(av.z, 0.f); av.w = fmaxf(av.w, 0.f);
            }
            As[c4 + 0][r] = av.x;
            As[c4 + 1][r] = av.y;
            As[c4 + 2][r] = av.z;
            As[c4 + 3][r] = av.w;
        }
#pragma unroll
        for (int l = 0; l < (BK * BN / 4) / 256; l++) {
            int idx = tid + l * 256;
            int r   = idx / (BN / 4);
            int c4  = (idx % (BN / 4)) * 4;
            *(float4*)&Bs[r][c4] = *(const float4*)(W + (size_t)(k0 + r) * N + c4);
        }
        __syncthreads();

#pragma unroll
        for (int k = 0; k < BK; k++) {
            float a[TM], b[TN];
#pragma unroll
            for (int i = 0; i < TM; i += 4)
                *(float4*)&a[i] = *(const float4*)&As[k][ty * TM + i];
#pragma unroll
            for (int j = 0; j < TN; j += 4)
                *(float4*)&b[j] = *(const float4*)&Bs[k][tx * TN + j];
#pragma unroll
            for (int i = 0; i < TM; i++)
#pragma unroll
                for (int j = 0; j < TN; j++)
                    acc[i][j] += a[i] * b[j];
        }
        __syncthreads();
    }

#pragma unroll
    for (int i = 0; i < TM; i++) {
        int gr = row0 + ty * TM + i;
        if (gr >= M) continue;
        float d = g_dis[gr];
#pragma unroll
        for (int j = 0; j < TN; j += 4) {
            float4 v = make_float4(acc[i][j] * d, acc[i][j + 1] * d,
                                   acc[i][j + 2] * d, acc[i][j + 3] * d);
            *(float4*)(XWS + (size_t)gr * N + tx * TN + j) = v;
        }
    }
}

// ---------------- CSR aggregation, D=128: one warp per node ----------------
// out[d] = dis[d] * ( xws[d] + sum_{s in nbr(d)} xws[s] ) + bias
__global__ void agg128(const float* __restrict__ xws,
                       const float* __restrict__ bias,
                       float* __restrict__ out, int n)
{
    int w = (blockIdx.x * blockDim.x + threadIdx.x) >> 5;
    int lane = threadIdx.x & 31;
    if (w >= n) return;
    int beg = g_off[w], end = g_off[w + 1];
    float dd = g_dis[w];

    float4 acc = *(const float4*)(xws + (size_t)w * 128 + lane * 4);

    int j = beg;
    for (; j + 4 <= end; j += 4) {
        int s0 = g_esrc[j], s1 = g_esrc[j + 1], s2 = g_esrc[j + 2], s3 = g_esrc[j + 3];
        float4 v0 = *(const float4*)(xws + (size_t)s0 * 128 + lane * 4);
        float4 v1 = *(const float4*)(xws + (size_t)s1 * 128 + lane * 4);
        float4 v2 = *(const float4*)(xws + (size_t)s2 * 128 + lane * 4);
        float4 v3 = *(const float4*)(xws + (size_t)s3 * 128 + lane * 4);
        acc.x += v0.x + v1.x + v2.x + v3.x;
        acc.y += v0.y + v1.y + v2.y + v3.y;
        acc.z += v0.z + v1.z + v2.z + v3.z;
        acc.w += v0.w + v1.w + v2.w + v3.w;
    }
    for (; j < end; j++) {
        int s = g_esrc[j];
        float4 v = *(const float4*)(xws + (size_t)s * 128 + lane * 4);
        acc.x += v.x; acc.y += v.y; acc.z += v.z; acc.w += v.w;
    }
    float4 b = *(const float4*)(bias + lane * 4);
    acc.x = acc.x * dd + b.x;
    acc.y = acc.y * dd + b.y;
    acc.z = acc.z * dd + b.z;
    acc.w = acc.w * dd + b.w;
    *(float4*)(out + (size_t)w * 128 + lane * 4) = acc;
}

// ---------------- CSR aggregation, D=64: one warp per node ----------------
__global__ void agg64(const float* __restrict__ xws,
                      const float* __restrict__ bias,
                      float* __restrict__ out, int n)
{
    int w = (blockIdx.x * blockDim.x + threadIdx.x) >> 5;
    int lane = threadIdx.x & 31;
    if (w >= n) return;
    int beg = g_off[w], end = g_off[w + 1];
    float dd = g_dis[w];

    float2 acc = *(const float2*)(xws + (size_t)w * 64 + lane * 2);

    int j = beg;
    for (; j + 4 <= end; j += 4) {
        int s0 = g_esrc[j], s1 = g_esrc[j + 1], s2 = g_esrc[j + 2], s3 = g_esrc[j + 3];
        float2 v0 = *(const float2*)(xws + (size_t)s0 * 64 + lane * 2);
        float2 v1 = *(const float2*)(xws + (size_t)s1 * 64 + lane * 2);
        float2 v2 = *(const float2*)(xws + (size_t)s2 * 64 + lane * 2);
        float2 v3 = *(const float2*)(xws + (size_t)s3 * 64 + lane * 2);
        acc.x += v0.x + v1.x + v2.x + v3.x;
        acc.y += v0.y + v1.y + v2.y + v3.y;
    }
    for (; j < end; j++) {
        int s = g_esrc[j];
        float2 v = *(const float2*)(xws + (size_t)s * 64 + lane * 2);
        acc.x += v.x; acc.y += v.y;
    }
    float2 b = *(const float2*)(bias + lane * 2);
    acc.x = acc.x * dd + b.x;
    acc.y = acc.y * dd + b.y;
    *(float2*)(out + (size_t)w * 64 + lane * 2) = acc;
}

extern "C" void kernel_launch(void* const* d_in, const int* in_sizes, int n_in,
                              void* d_out, int out_size)
{
    const float* x  = (const float*)d_in[0];
    const int*   ei = (const int*)  d_in[1];
    const float* W1 = (const float*)d_in[2];
    const float* b1 = (const float*)d_in[3];
    const float* W2 = (const float*)d_in[4];
    const float* b2 = (const float*)d_in[5];
    float* out = (float*)d_out;

    const int N = in_sizes[0] / DIN;   // 50000
    const int E = in_sizes[1] / 2;     // 800000
    const int* src = ei;
    const int* dst = ei + E;

    float *xw1, *agg1, *xw2;
    cudaGetSymbolAddress((void**)&xw1,  g_xw1);
    cudaGetSymbolAddress((void**)&agg1, g_agg1);
    cudaGetSymbolAddress((void**)&xw2,  g_xw2);

    const int nb = (N + 1023) / 1024;

    // CSR build + norms (hierarchical scan)
    k_init <<<(N + 255) / 256, 256>>>(N);
    k_hist <<<(E + 255) / 256, 256>>>(dst, E);
    k_scanA<<<nb, 1024>>>(N);
    k_scanB<<<1, 1>>>(N, nb);
    k_scanC<<<nb, 1024>>>(N);
    k_fill <<<(E + 255) / 256, 256>>>(src, dst, E);

    const int gemm_grid = (N + 127) / 128;

    // layer 1: xw1 = (x @ W1) * dis ; agg1 = dis*(self+nbr sum) + b1
    gemm_xws<128, 8, false><<<gemm_grid, 256>>>(x, W1, xw1, N, DIN, DHID);
    agg128<<<(N * 32 + 255) / 256, 256>>>(xw1, b1, agg1, N);

    // layer 2: xw2 = (relu(agg1) @ W2) * dis ; out = dis*(self+nbr sum) + b2
    gemm_xws<64, 4, true><<<gemm_grid, 256>>>(agg1, W2, xw2, N, DHID, DOUT);
    agg64<<<(N * 32 + 255) / 256, 256>>>(xw2, b2, out, N);
}

// round 4
// speedup vs baseline: 1.7663x; 1.1921x over previous
#include <cuda_runtime.h>
#include <cstddef>

#define NN 50000
#define NE 800000
#define DIN 128
#define DHID 128
#define DOUT 64
#define NB   ((NN + 1023) / 1024)   // 49 scan blocks

// ---------------- scratch (__device__ globals; no allocation) ----------------
__device__ float g_xw1[(size_t)NN * DHID];   // RAW x@W1 (not dis-scaled)
__device__ float g_agg1[(size_t)NN * DHID];
__device__ float g_xw2[(size_t)NN * DOUT];   // (relu(agg1)@W2) * dis[row]
__device__ float g_dis[NN];
__device__ int   g_cnt[NN];
__device__ int   g_cur[NN];
__device__ int   g_off[NN + 1];
__device__ int   g_esrc[NE];
__device__ int   g_bsum[NB];
__device__ int   g_bpre[NB];

// ---------------- CSR build ----------------
__global__ void k_init(int n) {
    int i = blockIdx.x * blockDim.x + threadIdx.x;
    if (i < n) g_cnt[i] = 0;
}

// histogram: 4 edges per thread via int4
__global__ void k_hist(const int* __restrict__ dst, int e4, int e) {
    int i = blockIdx.x * blockDim.x + threadIdx.x;
    if (i < e4) {
        int4 d = *(const int4*)(dst + i * 4);
        atomicAdd(&g_cnt[d.x], 1);
        atomicAdd(&g_cnt[d.y], 1);
        atomicAdd(&g_cnt[d.z], 1);
        atomicAdd(&g_cnt[d.w], 1);
    }
    // tail
    int t = e4 * 4 + i;
    if (i < (e - e4 * 4)) atomicAdd(&g_cnt[dst[t]], 1);
}

// phase A: per-block exclusive scan of 1024 counts; block total to g_bsum
__global__ void k_scanA(int n) {
    __shared__ int warpsum[32];
    const int tid = threadIdx.x, lane = tid & 31, wid = tid >> 5;
    int i = blockIdx.x * 1024 + tid;
    int v = (i < n) ? g_cnt[i] : 0;
    int x = v;
#pragma unroll
    for (int o = 1; o < 32; o <<= 1) {
        int t = __shfl_up_sync(0xFFFFFFFFu, x, o);
        if (lane >= o) x += t;
    }
    if (lane == 31) warpsum[wid] = x;
    __syncthreads();
    if (wid == 0) {
        int w = warpsum[lane];
#pragma unroll
        for (int o = 1; o < 32; o <<= 1) {
            int t = __shfl_up_sync(0xFFFFFFFFu, w, o);
            if (lane >= o) w += t;
        }
        warpsum[lane] = w;
    }
    __syncthreads();
    int warpbase = (wid == 0) ? 0 : warpsum[wid - 1];
    if (i < n) g_off[i] = warpbase + x - v;      // local exclusive
    if (tid == 1023) g_bsum[blockIdx.x] = warpsum[31];
}

// phase B: single-warp exclusive scan of NB block sums (2 per lane)
__global__ void k_scanB(int n, int nb) {
    int lane = threadIdx.x;      // 32 threads
    int i0 = 2 * lane, i1 = 2 * lane + 1;
    int v0 = (i0 < nb) ? g_bsum[i0] : 0;
    int v1 = (i1 < nb) ? g_bsum[i1] : 0;
    int s = v0 + v1;
    int x = s;
#pragma unroll
    for (int o = 1; o < 32; o <<= 1) {
        int t = __shfl_up_sync(0xFFFFFFFFu, x, o);
        if (lane >= o) x += t;
    }
    int excl = x - s;
    if (i0 < nb) g_bpre[i0] = excl;
    if (i1 < nb) g_bpre[i1] = excl + v0;
    if (lane == 31) g_off[n] = x;
}

// phase C: add block prefix; compute dis; init fill cursor to offset
__global__ void k_scanC(int n) {
    int i = blockIdx.x * blockDim.x + threadIdx.x;
    if (i < n) {
        int o = g_off[i] + g_bpre[i >> 10];
        g_off[i] = o;
        g_cur[i] = o;
        g_dis[i] = rsqrtf((float)g_cnt[i] + 1.0f);
    }
}

__global__ void k_fill(const int* __restrict__ src, const int* __restrict__ dst, int e) {
    int i = blockIdx.x * blockDim.x + threadIdx.x;
    if (i < e) {
        int p = atomicAdd(&g_cur[dst[i]], 1);
        g_esrc[p] = src[i];
    }
}

// ---------------- SGEMM: XWS = (op(A) @ W) [* dis[row] if SCALE] ----------------
template <int BN, int TN, bool RELU_IN, bool SCALE_DIS>
__global__ void __launch_bounds__(256, 2)
gemm_xws(const float* __restrict__ A, const float* __restrict__ W,
         float* __restrict__ XWS, int M, int K, int N)
{
    constexpr int BM = 128, BK = 16, TM = 8;
    __shared__ float As[BK][BM];
    __shared__ float Bs[BK][BN];

    const int tid  = threadIdx.x;           // 256 threads
    const int row0 = blockIdx.x * BM;
    const int tx   = tid & 15;
    const int ty   = tid >> 4;

    float acc[TM][TN];
#pragma unroll
    for (int i = 0; i < TM; i++)
#pragma unroll
        for (int j = 0; j < TN; j++) acc[i][j] = 0.0f;

    for (int k0 = 0; k0 < K; k0 += BK) {
#pragma unroll
        for (int l = 0; l < 2; l++) {
            int idx = tid + l * 256;
            int r   = idx >> 2;
            int c4  = (idx & 3) * 4;
            float4 av = make_float4(0.f, 0.f, 0.f, 0.f);
            int gr = row0 + r;
            if (gr < M) av = *(const float4*)(A + (size_t)gr * K + k0 + c4);
            if (RELU_IN) {
                av.x = fmaxf(av.x, 0.f); av.y = fmaxf(av.y, 0.f);
                av.z = fmaxf(av.z, 0.f); av.w = fmaxf(av.w, 0.f);
            }
            As[c4 + 0][r] = av.x;
            As[c4 + 1][r] = av.y;
            As[c4 + 2][r] = av.z;
            As[c4 + 3][r] = av.w;
        }
#pragma unroll
        for (int l = 0; l < (BK * BN / 4) / 256; l++) {
            int idx = tid + l * 256;
            int r   = idx / (BN / 4);
            int c4  = (idx % (BN / 4)) * 4;
            *(float4*)&Bs[r][c4] = *(const float4*)(W + (size_t)(k0 + r) * N + c4);
        }
        __syncthreads();

#pragma unroll
        for (int k = 0; k < BK; k++) {
            float a[TM], b[TN];
#pragma unroll
            for (int i = 0; i < TM; i += 4)
                *(float4*)&a[i] = *(const float4*)&As[k][ty * TM + i];
#pragma unroll
            for (int j = 0; j < TN; j += 4)
                *(float4*)&b[j] = *(const float4*)&Bs[k][tx * TN + j];
#pragma unroll
            for (int i = 0; i < TM; i++)
#pragma unroll
                for (int j = 0; j < TN; j++)
                    acc[i][j] += a[i] * b[j];
        }
        __syncthreads();
    }

#pragma unroll
    for (int i = 0; i < TM; i++) {
        int gr = row0 + ty * TM + i;
        if (gr >= M) continue;
        float d = SCALE_DIS ? g_dis[gr] : 1.0f;
#pragma unroll
        for (int j = 0; j < TN; j += 4) {
            float4 v;
            if (SCALE_DIS)
                v = make_float4(acc[i][j] * d, acc[i][j + 1] * d,
                                acc[i][j + 2] * d, acc[i][j + 3] * d);
            else
                v = make_float4(acc[i][j], acc[i][j + 1], acc[i][j + 2], acc[i][j + 3]);
            *(float4*)(XWS + (size_t)gr * N + tx * TN + j) = v;
        }
    }
}

// ---------------- CSR aggregation, D=128 (xw RAW): one warp per node --------
// out[d] = dis[d]*( xw[d]*dis[d] + sum_s xw[s]*dis[s] ) + bias
__global__ void agg128(const float* __restrict__ xw,
                       const float* __restrict__ bias,
                       float* __restrict__ out, int n)
{
    int w = (blockIdx.x * blockDim.x + threadIdx.x) >> 5;
    int lane = threadIdx.x & 31;
    if (w >= n) return;
    int beg = g_off[w], end = g_off[w + 1];
    float dd = g_dis[w];

    float4 acc = *(const float4*)(xw + (size_t)w * 128 + lane * 4);
    acc.x *= dd; acc.y *= dd; acc.z *= dd; acc.w *= dd;

    int j = beg;
    for (; j + 4 <= end; j += 4) {
        int s0 = g_esrc[j], s1 = g_esrc[j + 1], s2 = g_esrc[j + 2], s3 = g_esrc[j + 3];
        float n0 = g_dis[s0], n1 = g_dis[s1], n2 = g_dis[s2], n3 = g_dis[s3];
        float4 v0 = *(const float4*)(xw + (size_t)s0 * 128 + lane * 4);
        float4 v1 = *(const float4*)(xw + (size_t)s1 * 128 + lane * 4);
        float4 v2 = *(const float4*)(xw + (size_t)s2 * 128 + lane * 4);
        float4 v3 = *(const float4*)(xw + (size_t)s3 * 128 + lane * 4);
        acc.x += v0.x * n0; acc.y += v0.y * n0; acc.z += v0.z * n0; acc.w += v0.w * n0;
        acc.x += v1.x * n1; acc.y += v1.y * n1; acc.z += v1.z * n1; acc.w += v1.w * n1;
        acc.x += v2.x * n2; acc.y += v2.y * n2; acc.z += v2.z * n2; acc.w += v2.w * n2;
        acc.x += v3.x * n3; acc.y += v3.y * n3; acc.z += v3.z * n3; acc.w += v3.w * n3;
    }
    for (; j < end; j++) {
        int s = g_esrc[j];
        float ns = g_dis[s];
        float4 v = *(const float4*)(xw + (size_t)s * 128 + lane * 4);
        acc.x += v.x * ns; acc.y += v.y * ns; acc.z += v.z * ns; acc.w += v.w * ns;
    }
    float4 b = *(const float4*)(bias + lane * 4);
    acc.x = acc.x * dd + b.x;
    acc.y = acc.y * dd + b.y;
    acc.z = acc.z * dd + b.z;
    acc.w = acc.w * dd + b.w;
    *(float4*)(out + (size_t)w * 128 + lane * 4) = acc;
}

// ---------------- CSR aggregation, D=64 (xws pre-scaled): one warp per node -
__global__ void agg64(const float* __restrict__ xws,
                      const float* __restrict__ bias,
                      float* __restrict__ out, int n)
{
    int w = (blockIdx.x * blockDim.x + threadIdx.x) >> 5;
    int lane = threadIdx.x & 31;
    if (w >= n) return;
    int beg = g_off[w], end = g_off[w + 1];
    float dd = g_dis[w];

    float2 acc = *(const float2*)(xws + (size_t)w * 64 + lane * 2);

    int j = beg;
    for (; j + 4 <= end; j += 4) {
        int s0 = g_esrc[j], s1 = g_esrc[j + 1], s2 = g_esrc[j + 2], s3 = g_esrc[j + 3];
        float2 v0 = *(const float2*)(xws + (size_t)s0 * 64 + lane * 2);
        float2 v1 = *(const float2*)(xws + (size_t)s1 * 64 + lane * 2);
        float2 v2 = *(const float2*)(xws + (size_t)s2 * 64 + lane * 2);
        float2 v3 = *(const float2*)(xws + (size_t)s3 * 64 + lane * 2);
        acc.x += v0.x + v1.x + v2.x + v3.x;
        acc.y += v0.y + v1.y + v2.y + v3.y;
    }
    for (; j < end; j++) {
        int s = g_esrc[j];
        float2 v = *(const float2*)(xws + (size_t)s * 64 + lane * 2);
        acc.x += v.x; acc.y += v.y;
    }
    float2 b = *(const float2*)(bias + lane * 2);
    acc.x = acc.x * dd + b.x;
    acc.y = acc.y * dd + b.y;
    *(float2*)(out + (size_t)w * 64 + lane * 2) = acc;
}

extern "C" void kernel_launch(void* const* d_in, const int* in_sizes, int n_in,
                              void* d_out, int out_size)
{
    const float* x  = (const float*)d_in[0];
    const int*   ei = (const int*)  d_in[1];
    const float* W1 = (const float*)d_in[2];
    const float* b1 = (const float*)d_in[3];
    const float* W2 = (const float*)d_in[4];
    const float* b2 = (const float*)d_in[5];
    float* out = (float*)d_out;

    const int N = in_sizes[0] / DIN;   // 50000
    const int E = in_sizes[1] / 2;     // 800000
    const int* src = ei;
    const int* dst = ei + E;

    float *xw1, *agg1, *xw2;
    cudaGetSymbolAddress((void**)&xw1,  g_xw1);
    cudaGetSymbolAddress((void**)&agg1, g_agg1);
    cudaGetSymbolAddress((void**)&xw2,  g_xw2);

    // Lazy side-stream/event creation (first call is the non-captured
    // correctness run; reused identically on every call thereafter).
    static cudaStream_t s_side = nullptr;
    static cudaEvent_t  s_fork = nullptr, s_join = nullptr;
    if (s_side == nullptr) {
        cudaStreamCreateWithFlags(&s_side, cudaStreamNonBlocking);
        cudaEventCreateWithFlags(&s_fork, cudaEventDisableTiming);
        cudaEventCreateWithFlags(&s_join, cudaEventDisableTiming);
    }

    const int nb = (N + 1023) / 1024;
    const int e4 = E / 4;
    const int gemm_grid = (N + 127) / 128;

    // ---- fork: CSR build chain on side stream, GEMM1 on main stream ----
    cudaEventRecord(s_fork, 0);
    cudaStreamWaitEvent(s_side, s_fork, 0);

    // side: CSR build + norms
    k_init <<<(N + 255) / 256, 256, 0, s_side>>>(N);
    k_hist <<<(e4 + 255) / 256, 256, 0, s_side>>>(dst, e4, E);
    k_scanA<<<nb, 1024, 0, s_side>>>(N);
    k_scanB<<<1, 32, 0, s_side>>>(N, nb);
    k_scanC<<<(N + 1023) / 1024, 1024, 0, s_side>>>(N);
    k_fill <<<(E + 255) / 256, 256, 0, s_side>>>(src, dst, E);
    cudaEventRecord(s_join, s_side);

    // main: layer-1 GEMM (independent of graph structure)
    gemm_xws<128, 8, false, false><<<gemm_grid, 256>>>(x, W1, xw1, N, DIN, DHID);

    // join
    cudaStreamWaitEvent(0, s_join, 0);

    // layer 1 aggregation: agg1 = dis*(self + sum xw1[s]*dis[s]) + b1
    agg128<<<(N * 32 + 255) / 256, 256>>>(xw1, b1, agg1, N);

    // layer 2: xw2 = (relu(agg1) @ W2) * dis ; out = dis*(self+nbr sum) + b2
    gemm_xws<64, 4, true, true><<<gemm_grid, 256>>>(agg1, W2, xw2, N, DHID, DOUT);
    agg64<<<(N * 32 + 255) / 256, 256>>>(xw2, b2, out, N);
}

// round 5
// speedup vs baseline: 1.7769x; 1.0060x over previous
#include <cuda_runtime.h>
#include <cstddef>

#define NN 50000
#define NE 800000
#define DIN 128
#define DHID 128
#define DOUT 64
#define NB   ((NN + 1023) / 1024)   // 49 scan blocks

// ---------------- scratch (__device__ globals; no allocation) ----------------
__device__ float g_xw1[(size_t)NN * DHID];   // RAW x@W1 (not dis-scaled)
__device__ float g_agg1[(size_t)NN * DHID];
__device__ float g_xw2[(size_t)NN * DOUT];   // (relu(agg1)@W2) * dis[row]
__device__ float g_dis[NN];
__device__ int   g_cnt[NN];
__device__ int   g_cur[NN];
__device__ int   g_off[NN + 1];
__device__ int   g_esrc[NE];
__device__ int   g_bsum[NB];

// ---------------- CSR build ----------------
__global__ void k_init(int n) {
    int i = blockIdx.x * blockDim.x + threadIdx.x;
    if (i < n) g_cnt[i] = 0;
}

// histogram: 4 edges per thread via int4
__global__ void k_hist(const int* __restrict__ dst, int e4, int e) {
    int i = blockIdx.x * blockDim.x + threadIdx.x;
    if (i < e4) {
        int4 d = *(const int4*)(dst + i * 4);
        atomicAdd(&g_cnt[d.x], 1);
        atomicAdd(&g_cnt[d.y], 1);
        atomicAdd(&g_cnt[d.z], 1);
        atomicAdd(&g_cnt[d.w], 1);
    }
    int t = e4 * 4 + i;
    if (i < (e - e4 * 4)) atomicAdd(&g_cnt[dst[t]], 1);
}

// phase A: per-block exclusive scan of 1024 counts; block total to g_bsum
__global__ void k_scanA(int n) {
    __shared__ int warpsum[32];
    const int tid = threadIdx.x, lane = tid & 31, wid = tid >> 5;
    int i = blockIdx.x * 1024 + tid;
    int v = (i < n) ? g_cnt[i] : 0;
    int x = v;
#pragma unroll
    for (int o = 1; o < 32; o <<= 1) {
        int t = __shfl_up_sync(0xFFFFFFFFu, x, o);
        if (lane >= o) x += t;
    }
    if (lane == 31) warpsum[wid] = x;
    __syncthreads();
    if (wid == 0) {
        int w = warpsum[lane];
#pragma unroll
        for (int o = 1; o < 32; o <<= 1) {
            int t = __shfl_up_sync(0xFFFFFFFFu, w, o);
            if (lane >= o) w += t;
        }
        warpsum[lane] = w;
    }
    __syncthreads();
    int warpbase = (wid == 0) ? 0 : warpsum[wid - 1];
    if (i < n) g_off[i] = warpbase + x - v;      // local exclusive
    if (tid == 1023) g_bsum[blockIdx.x] = warpsum[31];
}

// phase C: each block computes its own prefix over g_bsum (<=64 sums),
// then adds it; computes dis; inits fill cursor. Last block writes g_off[n].
__global__ void k_scanC(int n, int nb) {
    __shared__ int s_pre, s_tot;
    const int tid = threadIdx.x, lane = tid & 31;
    if (tid < 32) {
        int i0 = 2 * lane, i1 = 2 * lane + 1;
        int v0 = (i0 < nb) ? g_bsum[i0] : 0;
        int v1 = (i1 < nb) ? g_bsum[i1] : 0;
        int p = 0, t = 0;
        p += (i0 < (int)blockIdx.x) ? v0 : 0;
        p += (i1 < (int)blockIdx.x) ? v1 : 0;
        t += v0 + v1;
#pragma unroll
        for (int o = 16; o > 0; o >>= 1) {
            p += __shfl_down_sync(0xFFFFFFFFu, p, o);
            t += __shfl_down_sync(0xFFFFFFFFu, t, o);
        }
        if (lane == 0) { s_pre = p; s_tot = t; }
    }
    __syncthreads();
    int pre = s_pre;
    int i = blockIdx.x * 1024 + tid;
    if (i < n) {
        int o = g_off[i] + pre;
        g_off[i] = o;
        g_cur[i] = o;
        g_dis[i] = rsqrtf((float)g_cnt[i] + 1.0f);
    }
    if ((int)blockIdx.x == nb - 1 && tid == 0) g_off[n] = s_tot;
}

__global__ void k_fill(const int* __restrict__ src, const int* __restrict__ dst, int e) {
    int i = blockIdx.x * blockDim.x + threadIdx.x;
    if (i < e) {
        int p = atomicAdd(&g_cur[dst[i]], 1);
        g_esrc[p] = src[i];
    }
}

// ---------------- packed f32x2 FMA helpers ----------------
__device__ __forceinline__ void fma2(unsigned long long& d,
                                     unsigned long long a,
                                     unsigned long long b) {
    asm("fma.rn.f32x2 %0, %1, %2, %0;" : "+l"(d) : "l"(a), "l"(b));
}
__device__ __forceinline__ unsigned long long bcast2(float a) {
    unsigned long long r;
    asm("mov.b64 %0, {%1, %1};" : "=l"(r) : "r"(__float_as_uint(a)));
    return r;
}

// ---------------- SGEMM (FFMA2): XWS = (op(A) @ W) [* dis[row]] ----------------
template <int BN, int TN, bool RELU_IN, bool SCALE_DIS>
__global__ void __launch_bounds__(256, 2)
gemm_xws(const float* __restrict__ A, const float* __restrict__ W,
         float* __restrict__ XWS, int M, int K, int N)
{
    constexpr int BM = 128, BK = 16, TM = 8;
    __shared__ float As[BK][BM];
    __shared__ float Bs[BK][BN];

    const int tid  = threadIdx.x;           // 256 threads
    const int row0 = blockIdx.x * BM;
    const int tx   = tid & 15;
    const int ty   = tid >> 4;

    unsigned long long acc2[TM][TN / 2];
#pragma unroll
    for (int i = 0; i < TM; i++)
#pragma unroll
        for (int j = 0; j < TN / 2; j++) acc2[i][j] = 0ULL;

    for (int k0 = 0; k0 < K; k0 += BK) {
#pragma unroll
        for (int l = 0; l < 2; l++) {
            int idx = tid + l * 256;
            int r   = idx >> 2;
            int c4  = (idx & 3) * 4;
            float4 av = make_float4(0.f, 0.f, 0.f, 0.f);
            int gr = row0 + r;
            if (gr < M) av = *(const float4*)(A + (size_t)gr * K + k0 + c4);
            if (RELU_IN) {
                av.x = fmaxf(av.x, 0.f); av.y = fmaxf(av.y, 0.f);
                av.z = fmaxf(av.z, 0.f); av.w = fmaxf(av.w, 0.f);
            }
            As[c4 + 0][r] = av.x;
            As[c4 + 1][r] = av.y;
            As[c4 + 2][r] = av.z;
            As[c4 + 3][r] = av.w;
        }
#pragma unroll
        for (int l = 0; l < (BK * BN / 4) / 256; l++) {
            int idx = tid + l * 256;
            int r   = idx / (BN / 4);
            int c4  = (idx % (BN / 4)) * 4;
            *(float4*)&Bs[r][c4] = *(const float4*)(W + (size_t)(k0 + r) * N + c4);
        }
        __syncthreads();

#pragma unroll
        for (int k = 0; k < BK; k++) {
            float a[TM];
            unsigned long long bp[TN / 2];
#pragma unroll
            for (int i = 0; i < TM; i += 4)
                *(float4*)&a[i] = *(const float4*)&As[k][ty * TM + i];
#pragma unroll
            for (int j = 0; j < TN / 2; j++)
                bp[j] = *(const unsigned long long*)&Bs[k][tx * TN + 2 * j];
#pragma unroll
            for (int i = 0; i < TM; i++) {
                unsigned long long ap = bcast2(a[i]);
#pragma unroll
                for (int j = 0; j < TN / 2; j++)
                    fma2(acc2[i][j], ap, bp[j]);
            }
        }
        __syncthreads();
    }

#pragma unroll
    for (int i = 0; i < TM; i++) {
        int gr = row0 + ty * TM + i;
        if (gr >= M) continue;
        float d = SCALE_DIS ? g_dis[gr] : 1.0f;
#pragma unroll
        for (int j = 0; j < TN / 2; j += 2) {
            float2 p0 = *(float2*)&acc2[i][j];
            float2 p1 = *(float2*)&acc2[i][j + 1];
            float4 v;
            if (SCALE_DIS)
                v = make_float4(p0.x * d, p0.y * d, p1.x * d, p1.y * d);
            else
                v = make_float4(p0.x, p0.y, p1.x, p1.y);
            *(float4*)(XWS + (size_t)gr * N + tx * TN + 2 * j) = v;
        }
    }
}

// ---------------- CSR aggregation, D=128 (xw RAW): one warp per node --------
__global__ void agg128(const float* __restrict__ xw,
                       const float* __restrict__ bias,
                       float* __restrict__ out, int n)
{
    int w = (blockIdx.x * blockDim.x + threadIdx.x) >> 5;
    int lane = threadIdx.x & 31;
    if (w >= n) return;
    int beg = g_off[w], end = g_off[w + 1];
    float dd = g_dis[w];

    float4 acc = *(const float4*)(xw + (size_t)w * 128 + lane * 4);
    acc.x *= dd; acc.y *= dd; acc.z *= dd; acc.w *= dd;

    int j = beg;
    for (; j + 4 <= end; j += 4) {
        int s0 = g_esrc[j], s1 = g_esrc[j + 1], s2 = g_esrc[j + 2], s3 = g_esrc[j + 3];
        float n0 = g_dis[s0], n1 = g_dis[s1], n2 = g_dis[s2], n3 = g_dis[s3];
        float4 v0 = *(const float4*)(xw + (size_t)s0 * 128 + lane * 4);
        float4 v1 = *(const float4*)(xw + (size_t)s1 * 128 + lane * 4);
        float4 v2 = *(const float4*)(xw + (size_t)s2 * 128 + lane * 4);
        float4 v3 = *(const float4*)(xw + (size_t)s3 * 128 + lane * 4);
        acc.x += v0.x * n0; acc.y += v0.y * n0; acc.z += v0.z * n0; acc.w += v0.w * n0;
        acc.x += v1.x * n1; acc.y += v1.y * n1; acc.z += v1.z * n1; acc.w += v1.w * n1;
        acc.x += v2.x * n2; acc.y += v2.y * n2; acc.z += v2.z * n2; acc.w += v2.w * n2;
        acc.x += v3.x * n3; acc.y += v3.y * n3; acc.z += v3.z * n3; acc.w += v3.w * n3;
    }
    for (; j < end; j++) {
        int s = g_esrc[j];
        float ns = g_dis[s];
        float4 v = *(const float4*)(xw + (size_t)s * 128 + lane * 4);
        acc.x += v.x * ns; acc.y += v.y * ns; acc.z += v.z * ns; acc.w += v.w * ns;
    }
    float4 b = *(const float4*)(bias + lane * 4);
    acc.x = acc.x * dd + b.x;
    acc.y = acc.y * dd + b.y;
    acc.z = acc.z * dd + b.z;
    acc.w = acc.w * dd + b.w;
    *(float4*)(out + (size_t)w * 128 + lane * 4) = acc;
}

// ---------------- CSR aggregation, D=64 (xws pre-scaled): one warp per node -
__global__ void agg64(const float* __restrict__ xws,
                      const float* __restrict__ bias,
                      float* __restrict__ out, int n)
{
    int w = (blockIdx.x * blockDim.x + threadIdx.x) >> 5;
    int lane = threadIdx.x & 31;
    if (w >= n) return;
    int beg = g_off[w], end = g_off[w + 1];
    float dd = g_dis[w];

    float2 acc = *(const float2*)(xws + (size_t)w * 64 + lane * 2);

    int j = beg;
    for (; j + 4 <= end; j += 4) {
        int s0 = g_esrc[j], s1 = g_esrc[j + 1], s2 = g_esrc[j + 2], s3 = g_esrc[j + 3];
        float2 v0 = *(const float2*)(xws + (size_t)s0 * 64 + lane * 2);
        float2 v1 = *(const float2*)(xws + (size_t)s1 * 64 + lane * 2);
        float2 v2 = *(const float2*)(xws + (size_t)s2 * 64 + lane * 2);
        float2 v3 = *(const float2*)(xws + (size_t)s3 * 64 + lane * 2);
        acc.x += v0.x + v1.x + v2.x + v3.x;
        acc.y += v0.y + v1.y + v2.y + v3.y;
    }
    for (; j < end; j++) {
        int s = g_esrc[j];
        float2 v = *(const float2*)(xws + (size_t)s * 64 + lane * 2);
        acc.x += v.x; acc.y += v.y;
    }
    float2 b = *(const float2*)(bias + lane * 2);
    acc.x = acc.x * dd + b.x;
    acc.y = acc.y * dd + b.y;
    *(float2*)(out + (size_t)w * 64 + lane * 2) = acc;
}

extern "C" void kernel_launch(void* const* d_in, const int* in_sizes, int n_in,
                              void* d_out, int out_size)
{
    const float* x  = (const float*)d_in[0];
    const int*   ei = (const int*)  d_in[1];
    const float* W1 = (const float*)d_in[2];
    const float* b1 = (const float*)d_in[3];
    const float* W2 = (const float*)d_in[4];
    const float* b2 = (const float*)d_in[5];
    float* out = (float*)d_out;

    const int N = in_sizes[0] / DIN;   // 50000
    const int E = in_sizes[1] / 2;     // 800000
    const int* src = ei;
    const int* dst = ei + E;

    float *xw1, *agg1, *xw2;
    cudaGetSymbolAddress((void**)&xw1,  g_xw1);
    cudaGetSymbolAddress((void**)&agg1, g_agg1);
    cudaGetSymbolAddress((void**)&xw2,  g_xw2);

    static cudaStream_t s_side = nullptr;
    static cudaEvent_t  s_fork = nullptr, s_join = nullptr;
    if (s_side == nullptr) {
        cudaStreamCreateWithFlags(&s_side, cudaStreamNonBlocking);
        cudaEventCreateWithFlags(&s_fork, cudaEventDisableTiming);
        cudaEventCreateWithFlags(&s_join, cudaEventDisableTiming);
    }

    const int nb = (N + 1023) / 1024;
    const int e4 = E / 4;
    const int gemm_grid = (N + 127) / 128;

    // ---- fork: CSR build chain on side stream, GEMM1 on main stream ----
    cudaEventRecord(s_fork, 0);
    cudaStreamWaitEvent(s_side, s_fork, 0);

    k_init <<<(N + 255) / 256, 256, 0, s_side>>>(N);
    k_hist <<<(e4 + 255) / 256, 256, 0, s_side>>>(dst, e4, E);
    k_scanA<<<nb, 1024, 0, s_side>>>(N);
    k_scanC<<<nb, 1024, 0, s_side>>>(N, nb);
    k_fill <<<(E + 255) / 256, 256, 0, s_side>>>(src, dst, E);
    cudaEventRecord(s_join, s_side);

    // main: layer-1 GEMM (independent of graph structure)
    gemm_xws<128, 8, false, false><<<gemm_grid, 256>>>(x, W1, xw1, N, DIN, DHID);

    cudaStreamWaitEvent(0, s_join, 0);

    // layer 1 aggregation
    agg128<<<(N * 32 + 255) / 256, 256>>>(xw1, b1, agg1, N);

    // layer 2
    gemm_xws<64, 4, true, true><<<gemm_grid, 256>>>(agg1, W2, xw2, N, DHID, DOUT);
    agg64<<<(N * 32 + 255) / 256, 256>>>(xw2, b2, out, N);
}

// round 6
// speedup vs baseline: 1.9812x; 1.1150x over previous
#include <cuda_runtime.h>
#include <cuda_fp16.h>
#include <cstddef>

#define NN 50000
#define NE 800000
#define DIN 128
#define DHID 128
#define DOUT 64
#define NB   ((NN + 1023) / 1024)   // 49 scan blocks

// ---------------- scratch (__device__ globals; no allocation) ----------------
__device__ __half g_xw1[(size_t)NN * DHID];   // fp16 x@W1 (RAW)
__device__ float  g_agg1[(size_t)NN * DHID];
__device__ __half g_xw2[(size_t)NN * DOUT];   // fp16 (relu(agg1)@W2)*dis
__device__ float  g_dis[NN];
__device__ int    g_cnt[NN];   // zero-init at load; restored to 0 by k_scanC
__device__ int    g_cur[NN];
__device__ int    g_off[NN + 1];
__device__ int    g_esrc[NE];
__device__ int    g_bsum[NB];

// ---------------- CSR build ----------------
// histogram: 4 edges per thread via int4
__global__ void k_hist(const int* __restrict__ dst, int e4, int e) {
    int i = blockIdx.x * blockDim.x + threadIdx.x;
    if (i < e4) {
        int4 d = *(const int4*)(dst + i * 4);
        atomicAdd(&g_cnt[d.x], 1);
        atomicAdd(&g_cnt[d.y], 1);
        atomicAdd(&g_cnt[d.z], 1);
        atomicAdd(&g_cnt[d.w], 1);
    }
    int t = e4 * 4 + i;
    if (i < (e - e4 * 4)) atomicAdd(&g_cnt[dst[t]], 1);
}

// phase A: per-block exclusive scan of 1024 counts; block total to g_bsum
__global__ void k_scanA(int n) {
    __shared__ int warpsum[32];
    const int tid = threadIdx.x, lane = tid & 31, wid = tid >> 5;
    int i = blockIdx.x * 1024 + tid;
    int v = (i < n) ? g_cnt[i] : 0;
    int x = v;
#pragma unroll
    for (int o = 1; o < 32; o <<= 1) {
        int t = __shfl_up_sync(0xFFFFFFFFu, x, o);
        if (lane >= o) x += t;
    }
    if (lane == 31) warpsum[wid] = x;
    __syncthreads();
    if (wid == 0) {
        int w = warpsum[lane];
#pragma unroll
        for (int o = 1; o < 32; o <<= 1) {
            int t = __shfl_up_sync(0xFFFFFFFFu, w, o);
            if (lane >= o) w += t;
        }
        warpsum[lane] = w;
    }
    __syncthreads();
    int warpbase = (wid == 0) ? 0 : warpsum[wid - 1];
    if (i < n) g_off[i] = warpbase + x - v;      // local exclusive
    if (tid == 1023) g_bsum[blockIdx.x] = warpsum[31];
}

// phase C: per-block prefix over g_bsum; add; dis; cursor; RESET g_cnt to 0.
__global__ void k_scanC(int n, int nb) {
    __shared__ int s_pre, s_tot;
    const int tid = threadIdx.x, lane = tid & 31;
    if (tid < 32) {
        int i0 = 2 * lane, i1 = 2 * lane + 1;
        int v0 = (i0 < nb) ? g_bsum[i0] : 0;
        int v1 = (i1 < nb) ? g_bsum[i1] : 0;
        int p = 0, t = 0;
        p += (i0 < (int)blockIdx.x) ? v0 : 0;
        p += (i1 < (int)blockIdx.x) ? v1 : 0;
        t += v0 + v1;
#pragma unroll
        for (int o = 16; o > 0; o >>= 1) {
            p += __shfl_down_sync(0xFFFFFFFFu, p, o);
            t += __shfl_down_sync(0xFFFFFFFFu, t, o);
        }
        if (lane == 0) { s_pre = p; s_tot = t; }
    }
    __syncthreads();
    int pre = s_pre;
    int i = blockIdx.x * 1024 + tid;
    if (i < n) {
        int c = g_cnt[i];
        int o = g_off[i] + pre;
        g_off[i] = o;
        g_cur[i] = o;
        g_dis[i] = rsqrtf((float)c + 1.0f);
        g_cnt[i] = 0;                        // restore for next replay
    }
    if ((int)blockIdx.x == nb - 1 && tid == 0) g_off[n] = s_tot;
}

__global__ void k_fill(const int* __restrict__ src, const int* __restrict__ dst, int e) {
    int i = blockIdx.x * blockDim.x + threadIdx.x;
    if (i < e) {
        int p = atomicAdd(&g_cur[dst[i]], 1);
        g_esrc[p] = src[i];
    }
}

// ---------------- packed f32x2 FMA helpers ----------------
__device__ __forceinline__ void fma2(unsigned long long& d,
                                     unsigned long long a,
                                     unsigned long long b) {
    asm("fma.rn.f32x2 %0, %1, %2, %0;" : "+l"(d) : "l"(a), "l"(b));
}
__device__ __forceinline__ unsigned long long bcast2(float a) {
    unsigned long long r;
    asm("mov.b64 %0, {%1, %1};" : "=l"(r) : "r"(__float_as_uint(a)));
    return r;
}

// ---------------- SGEMM (FFMA2): XWS(half) = (op(A) @ W) [* dis[row]] --------
template <int BN, int TN, bool RELU_IN, bool SCALE_DIS>
__global__ void __launch_bounds__(256, 2)
gemm_xws(const float* __restrict__ A, const float* __restrict__ W,
         __half* __restrict__ XWS, int M, int K, int N)
{
    constexpr int BM = 128, BK = 16, TM = 8;
    __shared__ float As[BK][BM];
    __shared__ float Bs[BK][BN];

    const int tid  = threadIdx.x;           // 256 threads
    const int row0 = blockIdx.x * BM;
    const int tx   = tid & 15;
    const int ty   = tid >> 4;

    unsigned long long acc2[TM][TN / 2];
#pragma unroll
    for (int i = 0; i < TM; i++)
#pragma unroll
        for (int j = 0; j < TN / 2; j++) acc2[i][j] = 0ULL;

    for (int k0 = 0; k0 < K; k0 += BK) {
#pragma unroll
        for (int l = 0; l < 2; l++) {
            int idx = tid + l * 256;
            int r   = idx >> 2;
            int c4  = (idx & 3) * 4;
            float4 av = make_float4(0.f, 0.f, 0.f, 0.f);
            int gr = row0 + r;
            if (gr < M) av = *(const float4*)(A + (size_t)gr * K + k0 + c4);
            if (RELU_IN) {
                av.x = fmaxf(av.x, 0.f); av.y = fmaxf(av.y, 0.f);
                av.z = fmaxf(av.z, 0.f); av.w = fmaxf(av.w, 0.f);
            }
            As[c4 + 0][r] = av.x;
            As[c4 + 1][r] = av.y;
            As[c4 + 2][r] = av.z;
            As[c4 + 3][r] = av.w;
        }
#pragma unroll
        for (int l = 0; l < (BK * BN / 4) / 256; l++) {
            int idx = tid + l * 256;
            int r   = idx / (BN / 4);
            int c4  = (idx % (BN / 4)) * 4;
            *(float4*)&Bs[r][c4] = *(const float4*)(W + (size_t)(k0 + r) * N + c4);
        }
        __syncthreads();

#pragma unroll
        for (int k = 0; k < BK; k++) {
            float a[TM];
            unsigned long long bp[TN / 2];
#pragma unroll
            for (int i = 0; i < TM; i += 4)
                *(float4*)&a[i] = *(const float4*)&As[k][ty * TM + i];
#pragma unroll
            for (int j = 0; j < TN / 2; j++)
                bp[j] = *(const unsigned long long*)&Bs[k][tx * TN + 2 * j];
#pragma unroll
            for (int i = 0; i < TM; i++) {
                unsigned long long ap = bcast2(a[i]);
#pragma unroll
                for (int j = 0; j < TN / 2; j++)
                    fma2(acc2[i][j], ap, bp[j]);
            }
        }
        __syncthreads();
    }

#pragma unroll
    for (int i = 0; i < TM; i++) {
        int gr = row0 + ty * TM + i;
        if (gr >= M) continue;
        float d = SCALE_DIS ? g_dis[gr] : 1.0f;
        __half2 h[TN / 2];
#pragma unroll
        for (int j = 0; j < TN / 2; j++) {
            float2 p = *(float2*)&acc2[i][j];
            h[j] = SCALE_DIS ? __floats2half2_rn(p.x * d, p.y * d)
                             : __floats2half2_rn(p.x, p.y);
        }
        __half* dstp = XWS + (size_t)gr * N + tx * TN;
        if (TN == 8) *(uint4*)dstp = *(uint4*)h;
        else         *(uint2*)dstp = *(uint2*)h;
    }
}

// ---------------- CSR aggregation, D=128 (half xw): one warp per node -------
// out[d] = dis[d]*( xw[d]*dis[d] + sum_s xw[s]*dis[s] ) + bias   (fp32 acc)
__global__ void agg128h(const __half* __restrict__ xw,
                        const float* __restrict__ bias,
                        float* __restrict__ out, int n)
{
    int w = (blockIdx.x * blockDim.x + threadIdx.x) >> 5;
    int lane = threadIdx.x & 31;
    if (w >= n) return;
    int beg = g_off[w], end = g_off[w + 1];
    float dd = g_dis[w];

    // self term: 4 halves per lane
    uint2 us = *(const uint2*)(xw + (size_t)w * 128 + lane * 4);
    float2 s0 = __half22float2(*(__half2*)&us.x);
    float2 s1 = __half22float2(*(__half2*)&us.y);
    float4 acc = make_float4(s0.x * dd, s0.y * dd, s1.x * dd, s1.y * dd);

    int j = beg;
    for (; j + 4 <= end; j += 4) {
        int e0 = g_esrc[j], e1 = g_esrc[j + 1], e2 = g_esrc[j + 2], e3 = g_esrc[j + 3];
        float n0 = g_dis[e0], n1 = g_dis[e1], n2 = g_dis[e2], n3 = g_dis[e3];
        uint2 u0 = *(const uint2*)(xw + (size_t)e0 * 128 + lane * 4);
        uint2 u1 = *(const uint2*)(xw + (size_t)e1 * 128 + lane * 4);
        uint2 u2 = *(const uint2*)(xw + (size_t)e2 * 128 + lane * 4);
        uint2 u3 = *(const uint2*)(xw + (size_t)e3 * 128 + lane * 4);
        float2 a0 = __half22float2(*(__half2*)&u0.x), b0 = __half22float2(*(__half2*)&u0.y);
        float2 a1 = __half22float2(*(__half2*)&u1.x), b1 = __half22float2(*(__half2*)&u1.y);
        float2 a2 = __half22float2(*(__half2*)&u2.x), b2 = __half22float2(*(__half2*)&u2.y);
        float2 a3 = __half22float2(*(__half2*)&u3.x), b3 = __half22float2(*(__half2*)&u3.y);
        acc.x += a0.x * n0 + a1.x * n1 + a2.x * n2 + a3.x * n3;
        acc.y += a0.y * n0 + a1.y * n1 + a2.y * n2 + a3.y * n3;
        acc.z += b0.x * n0 + b1.x * n1 + b2.x * n2 + b3.x * n3;
        acc.w += b0.y * n0 + b1.y * n1 + b2.y * n2 + b3.y * n3;
    }
    for (; j < end; j++) {
        int s = g_esrc[j];
        float ns = g_dis[s];
        uint2 u = *(const uint2*)(xw + (size_t)s * 128 + lane * 4);
        float2 a = __half22float2(*(__half2*)&u.x);
        float2 b = __half22float2(*(__half2*)&u.y);
        acc.x += a.x * ns; acc.y += a.y * ns; acc.z += b.x * ns; acc.w += b.y * ns;
    }
    float4 bv = *(const float4*)(bias + lane * 4);
    acc.x = acc.x * dd + bv.x;
    acc.y = acc.y * dd + bv.y;
    acc.z = acc.z * dd + bv.z;
    acc.w = acc.w * dd + bv.w;
    *(float4*)(out + (size_t)w * 128 + lane * 4) = acc;
}

// ---------------- CSR aggregation, D=64 (half xws pre-scaled) ---------------
__global__ void agg64h(const __half* __restrict__ xws,
                       const float* __restrict__ bias,
                       float* __restrict__ out, int n)
{
    int w = (blockIdx.x * blockDim.x + threadIdx.x) >> 5;
    int lane = threadIdx.x & 31;
    if (w >= n) return;
    int beg = g_off[w], end = g_off[w + 1];
    float dd = g_dis[w];

    float2 acc = __half22float2(*(const __half2*)(xws + (size_t)w * 64 + lane * 2));

    int j = beg;
    for (; j + 4 <= end; j += 4) {
        int e0 = g_esrc[j], e1 = g_esrc[j + 1], e2 = g_esrc[j + 2], e3 = g_esrc[j + 3];
        float2 v0 = __half22float2(*(const __half2*)(xws + (size_t)e0 * 64 + lane * 2));
        float2 v1 = __half22float2(*(const __half2*)(xws + (size_t)e1 * 64 + lane * 2));
        float2 v2 = __half22float2(*(const __half2*)(xws + (size_t)e2 * 64 + lane * 2));
        float2 v3 = __half22float2(*(const __half2*)(xws + (size_t)e3 * 64 + lane * 2));
        acc.x += v0.x + v1.x + v2.x + v3.x;
        acc.y += v0.y + v1.y + v2.y + v3.y;
    }
    for (; j < end; j++) {
        int s = g_esrc[j];
        float2 v = __half22float2(*(const __half2*)(xws + (size_t)s * 64 + lane * 2));
        acc.x += v.x; acc.y += v.y;
    }
    float2 b = *(const float2*)(bias + lane * 2);
    acc.x = acc.x * dd + b.x;
    acc.y = acc.y * dd + b.y;
    *(float2*)(out + (size_t)w * 64 + lane * 2) = acc;
}

extern "C" void kernel_launch(void* const* d_in, const int* in_sizes, int n_in,
                              void* d_out, int out_size)
{
    const float* x  = (const float*)d_in[0];
    const int*   ei = (const int*)  d_in[1];
    const float* W1 = (const float*)d_in[2];
    const float* b1 = (const float*)d_in[3];
    const float* W2 = (const float*)d_in[4];
    const float* b2 = (const float*)d_in[5];
    float* out = (float*)d_out;

    const int N = in_sizes[0] / DIN;   // 50000
    const int E = in_sizes[1] / 2;     // 800000
    const int* src = ei;
    const int* dst = ei + E;

    __half *xw1, *xw2;
    float  *agg1;
    cudaGetSymbolAddress((void**)&xw1,  g_xw1);
    cudaGetSymbolAddress((void**)&agg1, g_agg1);
    cudaGetSymbolAddress((void**)&xw2,  g_xw2);

    static cudaStream_t s_side = nullptr;
    static cudaEvent_t  s_fork = nullptr, s_join = nullptr;
    if (s_side == nullptr) {
        cudaStreamCreateWithFlags(&s_side, cudaStreamNonBlocking);
        cudaEventCreateWithFlags(&s_fork, cudaEventDisableTiming);
        cudaEventCreateWithFlags(&s_join, cudaEventDisableTiming);
    }

    const int nb = (N + 1023) / 1024;
    const int e4 = E / 4;
    const int gemm_grid = (N + 127) / 128;

    // ---- fork: CSR build chain on side stream, GEMM1 on main stream ----
    cudaEventRecord(s_fork, 0);
    cudaStreamWaitEvent(s_side, s_fork, 0);

    k_hist <<<(e4 + 255) / 256, 256, 0, s_side>>>(dst, e4, E);
    k_scanA<<<nb, 1024, 0, s_side>>>(N);
    k_scanC<<<nb, 1024, 0, s_side>>>(N, nb);
    k_fill <<<(E + 255) / 256, 256, 0, s_side>>>(src, dst, E);
    cudaEventRecord(s_join, s_side);

    // main: layer-1 GEMM (independent of graph structure), fp16 output
    gemm_xws<128, 8, false, false><<<gemm_grid, 256>>>(x, W1, xw1, N, DIN, DHID);

    cudaStreamWaitEvent(0, s_join, 0);

    // layer 1 aggregation (fp16 gathers, fp32 accumulate/output)
    agg128h<<<(N * 32 + 255) / 256, 256>>>(xw1, b1, agg1, N);

    // layer 2: fp16 output scaled by dis
    gemm_xws<64, 4, true, true><<<gemm_grid, 256>>>(agg1, W2, xw2, N, DHID, DOUT);
    agg64h<<<(N * 32 + 255) / 256, 256>>>(xw2, b2, out, N);
}